// round 1
// baseline (speedup 1.0000x reference)
#include <cuda_runtime.h>

// Problem constants
#define KK      32
#define HH      4096
#define OUTN    4065          // HH - KK + 1
#define EPSV    1e-8f

// Tiling
#define WC       1024         // output columns per strip
#define NSTRIP   4            // 4 * 1024 = 4096 >= 4065
#define THREADS  256
#define SEG      4            // output cols per thread (consecutive)
#define ROWTILES 37
#define ROUT     110          // 37 * 110 = 4070 >= 4065
#define WIN      (WC + KK - 1)   // 1055 input cols per strip row
#define PF       5            // ceil(WIN / THREADS)
#define DROWSZ   1088         // WIN + WIN/32 + 1 (skewed size)

// smem word budget: img(1024) + 2*drow(2*1088) + hist(32*256 float4 = 32768 floats)
#define SMEM_FLOATS (1024 + 2 * DROWSZ + 32 * 256 * 4)

__device__ __forceinline__ int skew(int i) { return i + (i >> 5); }

__device__ __forceinline__ void prefetch_row(float sv[PF], float vv[PF],
                                             const float* __restrict__ som,
                                             const float* __restrict__ var,
                                             int gr, int c0, int t, int maxi,
                                             bool rowvalid)
{
    const float* srow = som + (size_t)gr * HH + c0;
    const float* vrow = var + (size_t)gr * HH + c0;
#pragma unroll
    for (int k = 0; k < PF; ++k) {
        int i = t + k * THREADS;
        bool ok = rowvalid && (i < WIN) && (i < maxi);
        sv[k] = ok ? __ldg(srow + i) : 0.0f;
        vv[k] = ok ? __ldg(vrow + i) : 1.0f;
    }
}

__device__ __forceinline__ void store_dist(float* __restrict__ dr,
                                           const float sv[PF], const float vv[PF],
                                           const float* __restrict__ s_img,
                                           int gr, int c0, int t)
{
    const float* irow = s_img + (gr & (KK - 1)) * KK;
#pragma unroll
    for (int k = 0; k < PF; ++k) {
        int i = t + k * THREADS;
        if (i < WIN) {
            float kv = irow[(c0 + i) & (KK - 1)];
            float d  = kv - sv[k];
            dr[skew(i)] = __fdividef(d * d, vv[k] + EPSV);
        }
    }
}

__global__ __launch_bounds__(THREADS, 1)
void som_boxdist_kernel(const float* __restrict__ img,
                        const float* __restrict__ som,
                        const float* __restrict__ var,
                        float* __restrict__ out)
{
    extern __shared__ __align__(16) float smem[];
    float*  s_img = smem;                         // 1024 floats
    float*  drow0 = smem + 1024;                  // DROWSZ floats
    float*  drow1 = drow0 + DROWSZ;               // DROWSZ floats
    float4* hist  = (float4*)(drow1 + DROWSZ);    // [32][256] float4

    const int t  = threadIdx.x;
    const int c0 = blockIdx.x * WC;
    const int r0 = blockIdx.y * ROUT;
    const int rows_out = min(ROUT, OUTN - r0);
    const int cols_out = min(WC,   OUTN - c0);
    const int rows_in  = rows_out + KK - 1;
    const int maxi     = HH - c0;                 // valid input-col limit (strip 3: 1024)

    // Load the 32x32 image once
    for (int i = t; i < KK * KK; i += THREADS) s_img[i] = img[i];

    // Depth-2 prefetch of raw rows
    float sA[PF], vA[PF], sB[PF], vB[PF];
    prefetch_row(sA, vA, som, var, r0,     c0, t, maxi, true);
    prefetch_row(sB, vB, som, var, min(r0 + 1, HH - 1), c0, t, maxi, rows_in > 1);

    const int cb = SEG * t;                       // thread's first local output col
    float vx = 0.f, vy = 0.f, vz = 0.f, vw = 0.f; // vertical running sums

    __syncthreads();  // s_img ready

    for (int ir = 0; ir < rows_in; ++ir) {
        const int gr = r0 + ir;
        float* dr = (ir & 1) ? drow1 : drow0;

        if ((ir & 1) == 0) {
            store_dist(dr, sA, vA, s_img, gr, c0, t);
            prefetch_row(sA, vA, som, var, min(gr + 2, HH - 1), c0, t, maxi,
                         (ir + 2) < rows_in);
        } else {
            store_dist(dr, sB, vB, s_img, gr, c0, t);
            prefetch_row(sB, vB, som, var, min(gr + 2, HH - 1), c0, t, maxi,
                         (ir + 2) < rows_in);
        }
        __syncthreads();

        // ---- horizontal 32-window (4 partial accumulators break the dep chain) ----
        float w0 = 0.f, w1 = 0.f, w2 = 0.f, w3 = 0.f;
#pragma unroll
        for (int x = 0; x < KK; x += 4) {
            w0 += dr[skew(cb + x + 0)];
            w1 += dr[skew(cb + x + 1)];
            w2 += dr[skew(cb + x + 2)];
            w3 += dr[skew(cb + x + 3)];
        }
        float4 h;
        h.x = (w0 + w1) + (w2 + w3);
        h.y = h.x + dr[skew(cb + KK + 0)] - dr[skew(cb + 0)];
        h.z = h.y + dr[skew(cb + KK + 1)] - dr[skew(cb + 1)];
        h.w = h.z + dr[skew(cb + KK + 2)] - dr[skew(cb + 2)];

        // ---- vertical sliding via 32-row history ring ----
        const int slot = ir & (KK - 1);
        float4 old = hist[slot * (WC / SEG) + t];
        if (ir < KK) { old.x = 0.f; old.y = 0.f; old.z = 0.f; old.w = 0.f; }
        vx += h.x - old.x;
        vy += h.y - old.y;
        vz += h.z - old.z;
        vw += h.w - old.w;
        hist[slot * (WC / SEG) + t] = h;

        // ---- emit output row once window is full ----
        if (ir >= KK - 1) {
            const int orow = r0 + ir - (KK - 1);
            float* op = out + (size_t)orow * OUTN + c0 + cb;
            if (cb + 0 < cols_out) op[0] = vx;
            if (cb + 1 < cols_out) op[1] = vy;
            if (cb + 2 < cols_out) op[2] = vz;
            if (cb + 3 < cols_out) op[3] = vw;
        }
    }
}

extern "C" void kernel_launch(void* const* d_in, const int* in_sizes, int n_in,
                              void* d_out, int out_size)
{
    (void)in_sizes; (void)n_in; (void)out_size;
    const float* img = (const float*)d_in[0];
    const float* som = (const float*)d_in[1];
    const float* var = (const float*)d_in[2];
    float* out = (float*)d_out;

    const size_t shmem = (size_t)SMEM_FLOATS * sizeof(float);  // 143,872 B
    cudaFuncSetAttribute(som_boxdist_kernel,
                         cudaFuncAttributeMaxDynamicSharedMemorySize, (int)shmem);

    dim3 grid(NSTRIP, ROWTILES);
    som_boxdist_kernel<<<grid, THREADS, shmem>>>(img, som, var, out);
}